// round 3
// baseline (speedup 1.0000x reference)
#include <cuda_runtime.h>
#include <cuda_bf16.h>

// Problem constants
#define B_ 4
#define C_ 256
#define N_ 4096   // H*W = 64*64

// Scratch for projected q, k, v, stored TRANSPOSED [b][n][c] as tf32 bit patterns.
// 3 * 4 * 4096 * 256 floats = 48 MB (static device array: allowed).
__device__ float g_qkv[3][(size_t)B_ * N_ * C_];

// ---------------------------------------------------------------------------
// tf32 helpers
// ---------------------------------------------------------------------------
__device__ __forceinline__ unsigned f2tf32(float f) {
    unsigned u;
    asm("cvt.rna.tf32.f32 %0, %1;" : "=r"(u) : "f"(f));
    return u;
}

// D += A*B, m16n8k8, tf32 inputs, f32 accumulate.
__device__ __forceinline__ void mma_tf32(float d[4],
                                         unsigned a0, unsigned a1, unsigned a2, unsigned a3,
                                         unsigned b0, unsigned b1) {
    asm volatile(
        "mma.sync.aligned.m16n8k8.row.col.f32.tf32.tf32.f32 "
        "{%0,%1,%2,%3}, {%4,%5,%6,%7}, {%8,%9}, {%0,%1,%2,%3};"
        : "+f"(d[0]), "+f"(d[1]), "+f"(d[2]), "+f"(d[3])
        : "r"(a0), "r"(a1), "r"(a2), "r"(a3), "r"(b0), "r"(b1));
}

// ---------------------------------------------------------------------------
// Kernel A: QKV projection (fp32 SIMT).
//   out_t[b][n][o] = tf32( sum_c W[o,c] * x[b,c,n] + bias[o] )   (TRANSPOSED)
// grid: (N/64, C/64, 3*B)   block: 256 threads (16x16), 4x4 micro-tile
// ---------------------------------------------------------------------------
__global__ __launch_bounds__(256) void proj_kernel(
    const float* __restrict__ x,
    const float* __restrict__ Wq, const float* __restrict__ bq,
    const float* __restrict__ Wk, const float* __restrict__ bk,
    const float* __restrict__ Wv, const float* __restrict__ bv)
{
    const int m = blockIdx.z / B_;       // 0=q 1=k 2=v
    const int b = blockIdx.z % B_;
    const float* Wm = (m == 0) ? Wq : (m == 1) ? Wk : Wv;
    const float* bm = (m == 0) ? bq : (m == 1) ? bk : bv;
    float* out = &g_qkv[m][(size_t)b * N_ * C_];   // [n][c] layout
    const float* xb = x + (size_t)b * C_ * N_;     // [c][n] layout

    const int o0 = blockIdx.y * 64;
    const int n0 = blockIdx.x * 64;

    __shared__ float Ws[16][68];   // [k][o]
    __shared__ float Xs[16][68];   // [k][n]

    const int tid = threadIdx.x;
    const int ty = tid >> 4;     // n groups of 4
    const int tx = tid & 15;     // o groups of 4

    float acc[4][4] = {};        // [n_sub][o_sub]

    for (int k0 = 0; k0 < C_; k0 += 16) {
        #pragma unroll
        for (int it = 0; it < 4; ++it) {
            int oo = (tid >> 4) + it * 16;
            int kk = tid & 15;
            Ws[kk][oo] = Wm[(o0 + oo) * C_ + k0 + kk];
        }
        #pragma unroll
        for (int it = 0; it < 4; ++it) {
            int kk = (tid >> 6) + it * 4;
            int nn = tid & 63;
            Xs[kk][nn] = xb[(size_t)(k0 + kk) * N_ + n0 + nn];
        }
        __syncthreads();

        #pragma unroll
        for (int k = 0; k < 16; ++k) {
            float4 a4 = *reinterpret_cast<const float4*>(&Xs[k][ty * 4]);  // n dim
            float4 b4 = *reinterpret_cast<const float4*>(&Ws[k][tx * 4]);  // o dim
            float a[4] = {a4.x, a4.y, a4.z, a4.w};
            float bb[4] = {b4.x, b4.y, b4.z, b4.w};
            #pragma unroll
            for (int r = 0; r < 4; ++r)
                #pragma unroll
                for (int u = 0; u < 4; ++u)
                    acc[r][u] += a[r] * bb[u];
        }
        __syncthreads();
    }

    const float4 bias4 = *reinterpret_cast<const float4*>(&bm[o0 + tx * 4]);
    #pragma unroll
    for (int r = 0; r < 4; ++r) {
        int n = n0 + ty * 4 + r;
        uint4 v;
        v.x = f2tf32(acc[r][0] + bias4.x);
        v.y = f2tf32(acc[r][1] + bias4.y);
        v.z = f2tf32(acc[r][2] + bias4.z);
        v.w = f2tf32(acc[r][3] + bias4.w);
        *reinterpret_cast<uint4*>(&out[(size_t)n * C_ + o0 + tx * 4]) = v;
    }
}

// ---------------------------------------------------------------------------
// Kernel B: tf32 mma flash attention + residual.
//   S[i,j] = sum_c q[c,i] k[c,j];  P = softmax_j(S);  O[i,c] = sum_j P[i,j] v[c,j]
//   out[b,c,i] = gamma*O[i,c]/l_i + x[b,c,i]
// grid: (N/64, B)  block: 256 threads = 8 warps
//   warp: i_sub = wid&3 (16 rows each), half = wid>>2 (32j for S / 128c for PV)
// mma m16n8k8 fragment maps (PTX ISA):
//   A: a0(r=g,c=t) a1(r=g+8,c=t) a2(r=g,c=t+4) a3(r=g+8,c=t+4)   g=lane>>2, t=lane&3
//   B: b0(k=t,n=g) b1(k=t+4,n=g)
//   C: c0(r=g,c=2t) c1(r=g,c=2t+1) c2(r=g+8,c=2t) c3(r=g+8,c=2t+1)
// smem strides chosen so fragment gathers are bank-conflict-free:
//   Qf[64][260], Ks[64][36], P[64][68]  (stride % 32 == 4 -> banks 4a+b distinct)
//   Vs[16][264]                          (stride % 32 == 8 -> banks 8b+a distinct)
// ---------------------------------------------------------------------------
#define QF_OFF   0                         // 64 x 260
#define KS_OFF   (QF_OFF + 64 * 260)       // 64 x 36
#define PP_OFF   (KS_OFF + 64 * 36)        // 64 x 68
#define VS_OFF   (PP_OFF + 64 * 68)        // 16 x 264
#define SMAX_OFF (VS_OFF + 16 * 264)       // 2 x 64
#define SSUM_OFF (SMAX_OFF + 128)          // 2 x 64
#define SMEM_FLOATS (SSUM_OFF + 128)       // 27776 floats = 111104 bytes

__global__ __launch_bounds__(256, 2) void attn_kernel(
    const float* __restrict__ x,
    const float* __restrict__ gamma,
    float* __restrict__ d_out)
{
    extern __shared__ float smem[];
    float*    Qf   = smem + QF_OFF;                                // tf32 bits
    float*    Ks   = smem + KS_OFF;                                // tf32 bits
    unsigned* Pp   = reinterpret_cast<unsigned*>(smem + PP_OFF);   // tf32 bits
    float*    Vs   = smem + VS_OFF;                                // tf32 bits
    float*    smax = smem + SMAX_OFF;
    float*    ssum = smem + SSUM_OFF;

    const int b  = blockIdx.y;
    const int i0 = blockIdx.x * 64;

    const float* qp = &g_qkv[0][(size_t)b * N_ * C_];  // [n][c]
    const float* kp = &g_qkv[1][(size_t)b * N_ * C_];
    const float* vp = &g_qkv[2][(size_t)b * N_ * C_];

    const int tid   = threadIdx.x;
    const int wid   = tid >> 5;
    const int lane  = tid & 31;
    const int i_sub = wid & 3;      // 16-row band
    const int half  = wid >> 2;     // 0/1
    const int g     = lane >> 2;    // groupID
    const int t     = lane & 3;     // threadID in group

    // ---- stage full Q tile once: Qf[i][c], 64 x 256, coalesced over c ----
    #pragma unroll
    for (int e = 0; e < 64; ++e) {
        int idx = tid + 256 * e;      // 0..16383
        int ii  = idx >> 8;
        int cc  = idx & 255;
        Qf[ii * 260 + cc] = qp[(size_t)(i0 + ii) * C_ + cc];
    }

    float o[16][4];                 // O frags: 16i x 128c per warp
    #pragma unroll
    for (int nf = 0; nf < 16; ++nf)
        #pragma unroll
        for (int r = 0; r < 4; ++r) o[nf][r] = 0.f;

    float mrow0 = -1e30f, mrow1 = -1e30f, lrow0 = 0.f, lrow1 = 0.f;

    const int rowL = i_sub * 16 + g;      // block-local row (this thread, +8 for second)

    __syncthreads();

    for (int jt = 0; jt < N_ / 64; ++jt) {
        const int j0 = jt * 64;

        // ======== S = Q^T K : warp tile 16i x 32j ========
        float sfr[4][4];
        #pragma unroll
        for (int nf = 0; nf < 4; ++nf)
            #pragma unroll
            for (int r = 0; r < 4; ++r) sfr[nf][r] = 0.f;

        for (int kc = 0; kc < 8; ++kc) {          // c chunks of 32
            // stage K chunk: Ks[j][c], 64 x 32, coalesced over c
            #pragma unroll
            for (int e = 0; e < 8; ++e) {
                int idx = tid + 256 * e;          // 0..2047
                int jj  = idx >> 5;
                int cc  = idx & 31;
                Ks[jj * 36 + cc] = kp[(size_t)(j0 + jj) * C_ + kc * 32 + cc];
            }
            __syncthreads();

            #pragma unroll
            for (int ks = 0; ks < 4; ++ks) {      // k-steps of 8 within chunk
                const int k0 = ks * 8;
                const int ar = i_sub * 16 + g;
                const int ac = kc * 32 + k0 + t;
                unsigned a0 = __float_as_uint(Qf[ar * 260 + ac]);
                unsigned a1 = __float_as_uint(Qf[(ar + 8) * 260 + ac]);
                unsigned a2 = __float_as_uint(Qf[ar * 260 + ac + 4]);
                unsigned a3 = __float_as_uint(Qf[(ar + 8) * 260 + ac + 4]);
                #pragma unroll
                for (int nf = 0; nf < 4; ++nf) {
                    const int bj = half * 32 + nf * 8 + g;
                    unsigned b0 = __float_as_uint(Ks[bj * 36 + k0 + t]);
                    unsigned b1 = __float_as_uint(Ks[bj * 36 + k0 + t + 4]);
                    mma_tf32(sfr[nf], a0, a1, a2, a3, b0, b1);
                }
            }
            __syncthreads();
        }

        // ======== online softmax ========
        float vmax0 = -1e30f, vmax1 = -1e30f;
        #pragma unroll
        for (int nf = 0; nf < 4; ++nf) {
            vmax0 = fmaxf(vmax0, fmaxf(sfr[nf][0], sfr[nf][1]));
            vmax1 = fmaxf(vmax1, fmaxf(sfr[nf][2], sfr[nf][3]));
        }
        vmax0 = fmaxf(vmax0, __shfl_xor_sync(0xffffffffu, vmax0, 1));
        vmax0 = fmaxf(vmax0, __shfl_xor_sync(0xffffffffu, vmax0, 2));
        vmax1 = fmaxf(vmax1, __shfl_xor_sync(0xffffffffu, vmax1, 1));
        vmax1 = fmaxf(vmax1, __shfl_xor_sync(0xffffffffu, vmax1, 2));
        if (t == 0) {
            smax[half * 64 + rowL]     = vmax0;
            smax[half * 64 + rowL + 8] = vmax1;
        }
        __syncthreads();

        const float m0 = fmaxf(mrow0, fmaxf(smax[rowL],     smax[64 + rowL]));
        const float m1 = fmaxf(mrow1, fmaxf(smax[rowL + 8], smax[64 + rowL + 8]));

        float sum0 = 0.f, sum1 = 0.f;
        #pragma unroll
        for (int nf = 0; nf < 4; ++nf) {
            sfr[nf][0] = __expf(sfr[nf][0] - m0);  sum0 += sfr[nf][0];
            sfr[nf][1] = __expf(sfr[nf][1] - m0);  sum0 += sfr[nf][1];
            sfr[nf][2] = __expf(sfr[nf][2] - m1);  sum1 += sfr[nf][2];
            sfr[nf][3] = __expf(sfr[nf][3] - m1);  sum1 += sfr[nf][3];
        }
        sum0 += __shfl_xor_sync(0xffffffffu, sum0, 1);
        sum0 += __shfl_xor_sync(0xffffffffu, sum0, 2);
        sum1 += __shfl_xor_sync(0xffffffffu, sum1, 1);
        sum1 += __shfl_xor_sync(0xffffffffu, sum1, 2);
        if (t == 0) {
            ssum[half * 64 + rowL]     = sum0;
            ssum[half * 64 + rowL + 8] = sum1;
        }

        // write P (tf32 bits) to smem: cols half*32 + nf*8 + 2t (+1)
        #pragma unroll
        for (int nf = 0; nf < 4; ++nf) {
            const int pc = half * 32 + nf * 8 + 2 * t;
            uint2 p01; p01.x = f2tf32(sfr[nf][0]); p01.y = f2tf32(sfr[nf][1]);
            uint2 p23; p23.x = f2tf32(sfr[nf][2]); p23.y = f2tf32(sfr[nf][3]);
            *reinterpret_cast<uint2*>(&Pp[rowL * 68 + pc])       = p01;
            *reinterpret_cast<uint2*>(&Pp[(rowL + 8) * 68 + pc]) = p23;
        }
        __syncthreads();

        const float f0 = __expf(mrow0 - m0);
        const float f1 = __expf(mrow1 - m1);
        mrow0 = m0;  mrow1 = m1;
        lrow0 = lrow0 * f0 + ssum[rowL]     + ssum[64 + rowL];
        lrow1 = lrow1 * f1 + ssum[rowL + 8] + ssum[64 + rowL + 8];
        #pragma unroll
        for (int nf = 0; nf < 16; ++nf) {
            o[nf][0] *= f0;  o[nf][1] *= f0;
            o[nf][2] *= f1;  o[nf][3] *= f1;
        }

        // ======== O += P * V^T : warp tile 16i x 128c ========
        for (int jc = 0; jc < 4; ++jc) {          // j chunks of 16
            // stage V chunk: Vs[j][c], 16 x 256, coalesced over c
            #pragma unroll
            for (int e = 0; e < 16; ++e) {
                int idx = tid + 256 * e;          // 0..4095
                int jj  = idx >> 8;
                int cc  = idx & 255;
                Vs[jj * 264 + cc] = vp[(size_t)(j0 + jc * 16 + jj) * C_ + cc];
            }
            __syncthreads();

            #pragma unroll
            for (int ks = 0; ks < 2; ++ks) {      // k-steps of 8 j
                const int pr = i_sub * 16 + g;
                const int pc = jc * 16 + ks * 8 + t;
                unsigned a0 = Pp[pr * 68 + pc];
                unsigned a1 = Pp[(pr + 8) * 68 + pc];
                unsigned a2 = Pp[pr * 68 + pc + 4];
                unsigned a3 = Pp[(pr + 8) * 68 + pc + 4];
                const int vj = ks * 8 + t;
                #pragma unroll
                for (int nf = 0; nf < 16; ++nf) {
                    const int vc = half * 128 + nf * 8 + g;
                    unsigned b0 = __float_as_uint(Vs[vj * 264 + vc]);
                    unsigned b1 = __float_as_uint(Vs[(vj + 4) * 264 + vc]);
                    mma_tf32(o[nf], a0, a1, a2, a3, b0, b1);
                }
            }
            __syncthreads();
        }
    }

    // ======== epilogue: out[b,c,i] = gamma*O/l + x ========
    const float gm = gamma[0];
    const float inv0 = 1.f / lrow0;
    const float inv1 = 1.f / lrow1;
    const float* xb = x + (size_t)b * C_ * N_;
    float* ob = d_out + (size_t)b * C_ * N_;
    const int ig = i0 + rowL;
    #pragma unroll
    for (int nf = 0; nf < 16; ++nf) {
        const int c = half * 128 + nf * 8 + 2 * t;
        size_t off = (size_t)c * N_ + ig;
        ob[off]          = gm * o[nf][0] * inv0 + xb[off];
        ob[off + N_]     = gm * o[nf][1] * inv0 + xb[off + N_];
        ob[off + 8]      = gm * o[nf][2] * inv1 + xb[off + 8];
        ob[off + N_ + 8] = gm * o[nf][3] * inv1 + xb[off + N_ + 8];
    }
}

// ---------------------------------------------------------------------------
extern "C" void kernel_launch(void* const* d_in, const int* in_sizes, int n_in,
                              void* d_out, int out_size)
{
    const float* x     = (const float*)d_in[0];
    const float* Wq    = (const float*)d_in[1];
    const float* bq    = (const float*)d_in[2];
    const float* Wk    = (const float*)d_in[3];
    const float* bk    = (const float*)d_in[4];
    const float* Wv    = (const float*)d_in[5];
    const float* bv    = (const float*)d_in[6];
    const float* gamma = (const float*)d_in[7];
    float* out = (float*)d_out;

    static int smem_set = 0;
    if (!smem_set) {
        cudaFuncSetAttribute(attn_kernel,
                             cudaFuncAttributeMaxDynamicSharedMemorySize,
                             SMEM_FLOATS * (int)sizeof(float));
        smem_set = 1;
    }

    dim3 gA(N_ / 64, C_ / 64, 3 * B_);
    proj_kernel<<<gA, 256>>>(x, Wq, bq, Wk, bk, Wv, bv);

    dim3 gB(N_ / 64, B_);
    attn_kernel<<<gB, 256, SMEM_FLOATS * (int)sizeof(float)>>>(x, gamma, out);
}

// round 12
// speedup vs baseline: 1.9069x; 1.9069x over previous
#include <cuda_runtime.h>
#include <cuda_bf16.h>

// Problem constants
#define B_ 4
#define C_ 256
#define N_ 4096   // H*W = 64*64
#define CW 128    // C/2 words per row (bf16x2)
#define NW 2048   // N/2 words per row (bf16x2)

// q,k stored [b][n][c] bf16 ; v stored [b][c][n] bf16  (packed as bf16x2 words)
__device__ unsigned g_qkv_u[3][(size_t)B_ * N_ * C_ / 2];   // 24 MB total

// ---------------------------------------------------------------------------
__device__ __forceinline__ unsigned pack_bf16x2(float lo, float hi) {
    unsigned d;
    asm("cvt.rn.bf16x2.f32 %0, %1, %2;" : "=r"(d) : "f"(hi), "f"(lo));
    return d;
}

// D += A*B, m16n8k16, bf16 inputs, f32 accumulate.
__device__ __forceinline__ void mma_bf16(float d[4],
                                         unsigned a0, unsigned a1, unsigned a2, unsigned a3,
                                         unsigned b0, unsigned b1) {
    asm volatile(
        "mma.sync.aligned.m16n8k16.row.col.f32.bf16.bf16.f32 "
        "{%0,%1,%2,%3}, {%4,%5,%6,%7}, {%8,%9}, {%0,%1,%2,%3};"
        : "+f"(d[0]), "+f"(d[1]), "+f"(d[2]), "+f"(d[3])
        : "r"(a0), "r"(a1), "r"(a2), "r"(a3), "r"(b0), "r"(b1));
}

// ---------------------------------------------------------------------------
// Kernel A: QKV projection (fp32 SIMT, bf16 output).
//   q,k: out[b][n][o] ; v: out[b][o][n]
// grid: (N/64, C/64, 3*B)   block: 256 threads (16x16), 4x4 micro-tile
// ---------------------------------------------------------------------------
__global__ __launch_bounds__(256) void proj_kernel(
    const float* __restrict__ x,
    const float* __restrict__ Wq, const float* __restrict__ bq,
    const float* __restrict__ Wk, const float* __restrict__ bk,
    const float* __restrict__ Wv, const float* __restrict__ bv)
{
    const int m = blockIdx.z / B_;       // 0=q 1=k 2=v
    const int b = blockIdx.z % B_;
    const float* Wm = (m == 0) ? Wq : (m == 1) ? Wk : Wv;
    const float* bm = (m == 0) ? bq : (m == 1) ? bk : bv;
    unsigned* out = &g_qkv_u[m][(size_t)b * N_ * CW];   // word base (q/k view)
    const float* xb = x + (size_t)b * C_ * N_;          // [c][n] layout

    const int o0 = blockIdx.y * 64;
    const int n0 = blockIdx.x * 64;

    __shared__ float Ws[16][68];   // [k][o]
    __shared__ float Xs[16][68];   // [k][n]

    const int tid = threadIdx.x;
    const int ty = tid >> 4;     // n groups of 4
    const int tx = tid & 15;     // o groups of 4

    float acc[4][4] = {};        // [n_sub][o_sub]

    for (int k0 = 0; k0 < C_; k0 += 16) {
        #pragma unroll
        for (int it = 0; it < 4; ++it) {
            int oo = (tid >> 4) + it * 16;
            int kk = tid & 15;
            Ws[kk][oo] = Wm[(o0 + oo) * C_ + k0 + kk];
        }
        #pragma unroll
        for (int it = 0; it < 4; ++it) {
            int kk = (tid >> 6) + it * 4;
            int nn = tid & 63;
            Xs[kk][nn] = xb[(size_t)(k0 + kk) * N_ + n0 + nn];
        }
        __syncthreads();

        #pragma unroll
        for (int k = 0; k < 16; ++k) {
            float4 a4 = *reinterpret_cast<const float4*>(&Xs[k][ty * 4]);
            float4 b4 = *reinterpret_cast<const float4*>(&Ws[k][tx * 4]);
            float a[4] = {a4.x, a4.y, a4.z, a4.w};
            float bb[4] = {b4.x, b4.y, b4.z, b4.w};
            #pragma unroll
            for (int r = 0; r < 4; ++r)
                #pragma unroll
                for (int u = 0; u < 4; ++u)
                    acc[r][u] += a[r] * bb[u];
        }
        __syncthreads();
    }

    const float4 bias4 = *reinterpret_cast<const float4*>(&bm[o0 + tx * 4]);
    const float bb4[4] = {bias4.x, bias4.y, bias4.z, bias4.w};

    if (m < 2) {
        // q,k : [n][c] layout, pack over o (c)
        #pragma unroll
        for (int r = 0; r < 4; ++r) {
            int n = n0 + ty * 4 + r;
            uint2 v;
            v.x = pack_bf16x2(acc[r][0] + bb4[0], acc[r][1] + bb4[1]);
            v.y = pack_bf16x2(acc[r][2] + bb4[2], acc[r][3] + bb4[3]);
            *reinterpret_cast<uint2*>(&out[(size_t)n * CW + (o0 + tx * 4) / 2]) = v;
        }
    } else {
        // v : [c][n] layout, pack over n
        #pragma unroll
        for (int u = 0; u < 4; ++u) {
            int o = o0 + tx * 4 + u;
            uint2 v;
            v.x = pack_bf16x2(acc[0][u] + bb4[u], acc[1][u] + bb4[u]);
            v.y = pack_bf16x2(acc[2][u] + bb4[u], acc[3][u] + bb4[u]);
            *reinterpret_cast<uint2*>(&out[(size_t)o * NW + (n0 + ty * 4) / 2]) = v;
        }
    }
}

// ---------------------------------------------------------------------------
// Kernel B: bf16 m16n8k16 flash attention + residual.
// grid: (N/64, B)  block: 256 threads = 8 warps
//   warp: i_sub = wid&3 (16 rows), half = wid>>2 (32j for S / 128c for PV)
// smem word strides ≡ 4 (mod 32) -> every fragment gather hits 32 distinct banks
// row strides are multiples of 4 words -> uint4 staging stores stay 16B-aligned
// ---------------------------------------------------------------------------
#define QF_OFF   0                          // 64 x 132 words  (q [i][cword])
#define KS_OFF   (QF_OFF + 64 * 132)        // 64 x 132 words  (k [j][cword])
#define VS_OFF   (KS_OFF + 64 * 132)        // 256 x 36 words  (v [c][jword])
#define PP_OFF   (VS_OFF + 256 * 36)        // 64 x 36 words   (p [i][jword])
#define SMAX_OFF (PP_OFF + 64 * 36)         // 2 x 64 floats
#define SSUM_OFF (SMAX_OFF + 128)           // 2 x 64 floats
#define SMEM_WORDS (SSUM_OFF + 128)         // 28672 words = 114688 bytes

__global__ __launch_bounds__(256, 2) void attn_kernel(
    const float* __restrict__ x,
    const float* __restrict__ gamma,
    float* __restrict__ d_out)
{
    extern __shared__ unsigned smem[];
    unsigned* Qf   = smem + QF_OFF;
    unsigned* Ks   = smem + KS_OFF;
    unsigned* Vs   = smem + VS_OFF;
    unsigned* Pp   = smem + PP_OFF;
    float*    smax = reinterpret_cast<float*>(smem + SMAX_OFF);
    float*    ssum = reinterpret_cast<float*>(smem + SSUM_OFF);

    const int b  = blockIdx.y;
    const int i0 = blockIdx.x * 64;

    const unsigned* qp = &g_qkv_u[0][(size_t)b * N_ * CW];  // [n][cword]
    const unsigned* kp = &g_qkv_u[1][(size_t)b * N_ * CW];  // [n][cword]
    const unsigned* vp = &g_qkv_u[2][(size_t)b * C_ * NW];  // [c][nword]

    const int tid   = threadIdx.x;
    const int wid   = tid >> 5;
    const int lane  = tid & 31;
    const int i_sub = wid & 3;      // 16-row band
    const int half  = wid >> 2;     // 0/1
    const int g     = lane >> 2;    // groupID (0..7)
    const int t     = lane & 3;     // thread in group (0..3)

    // ---- stage full Q tile once: Qf[i][cw], 64 x 128 words, uint4 ----
    #pragma unroll
    for (int e = 0; e < 8; ++e) {
        int idx = tid + 256 * e;      // 0..2047 uint4s
        int ii  = idx >> 5;           // row 0..63
        int w4  = idx & 31;           // uint4 within row
        *reinterpret_cast<uint4*>(&Qf[ii * 132 + w4 * 4]) =
            *reinterpret_cast<const uint4*>(&qp[(size_t)(i0 + ii) * CW + w4 * 4]);
    }

    float o[16][4];                 // O frags: 16i x 128c per warp
    #pragma unroll
    for (int nf = 0; nf < 16; ++nf)
        #pragma unroll
        for (int r = 0; r < 4; ++r) o[nf][r] = 0.f;

    float mrow0 = -1e30f, mrow1 = -1e30f, lrow0 = 0.f, lrow1 = 0.f;

    const int rowL = i_sub * 16 + g;      // block-local row (+8 for second row)

    __syncthreads();

    for (int jt = 0; jt < N_ / 64; ++jt) {
        const int j0 = jt * 64;

        __syncthreads();   // prev iteration's PV reads of Vs/Pp complete

        // ---- stage K tile: Ks[j][cw], 64 x 128 words, uint4 ----
        #pragma unroll
        for (int e = 0; e < 8; ++e) {
            int idx = tid + 256 * e;
            int jj  = idx >> 5;
            int w4  = idx & 31;
            *reinterpret_cast<uint4*>(&Ks[jj * 132 + w4 * 4]) =
                *reinterpret_cast<const uint4*>(&kp[(size_t)(j0 + jj) * CW + w4 * 4]);
        }
        // ---- stage V tile: Vs[c][jw], 256 x 32 words, uint4 ----
        #pragma unroll
        for (int e = 0; e < 8; ++e) {
            int idx = tid + 256 * e;      // 0..2047 uint4s
            int cc  = idx >> 3;           // channel 0..255
            int w4  = idx & 7;            // uint4 within row
            *reinterpret_cast<uint4*>(&Vs[cc * 36 + w4 * 4]) =
                *reinterpret_cast<const uint4*>(&vp[(size_t)cc * NW + j0 / 2 + w4 * 4]);
        }
        __syncthreads();

        // ======== S = Q^T K : warp tile 16i x 32j ========
        float sfr[4][4];
        #pragma unroll
        for (int nf = 0; nf < 4; ++nf)
            #pragma unroll
            for (int r = 0; r < 4; ++r) sfr[nf][r] = 0.f;

        const int ar = i_sub * 16 + g;
        #pragma unroll
        for (int ks = 0; ks < 16; ++ks) {          // k-steps of 16 c
            const int kw = ks * 8;
            unsigned a0 = Qf[ar * 132 + kw + t];
            unsigned a1 = Qf[(ar + 8) * 132 + kw + t];
            unsigned a2 = Qf[ar * 132 + kw + t + 4];
            unsigned a3 = Qf[(ar + 8) * 132 + kw + t + 4];
            #pragma unroll
            for (int nf = 0; nf < 4; ++nf) {
                const int bj = half * 32 + nf * 8 + g;
                unsigned b0 = Ks[bj * 132 + kw + t];
                unsigned b1 = Ks[bj * 132 + kw + t + 4];
                mma_bf16(sfr[nf], a0, a1, a2, a3, b0, b1);
            }
        }

        // ======== online softmax ========
        float vmax0 = -1e30f, vmax1 = -1e30f;
        #pragma unroll
        for (int nf = 0; nf < 4; ++nf) {
            vmax0 = fmaxf(vmax0, fmaxf(sfr[nf][0], sfr[nf][1]));
            vmax1 = fmaxf(vmax1, fmaxf(sfr[nf][2], sfr[nf][3]));
        }
        vmax0 = fmaxf(vmax0, __shfl_xor_sync(0xffffffffu, vmax0, 1));
        vmax0 = fmaxf(vmax0, __shfl_xor_sync(0xffffffffu, vmax0, 2));
        vmax1 = fmaxf(vmax1, __shfl_xor_sync(0xffffffffu, vmax1, 1));
        vmax1 = fmaxf(vmax1, __shfl_xor_sync(0xffffffffu, vmax1, 2));
        if (t == 0) {
            smax[half * 64 + rowL]     = vmax0;
            smax[half * 64 + rowL + 8] = vmax1;
        }
        __syncthreads();

        const float m0 = fmaxf(mrow0, fmaxf(smax[rowL],     smax[64 + rowL]));
        const float m1 = fmaxf(mrow1, fmaxf(smax[rowL + 8], smax[64 + rowL + 8]));

        float sum0 = 0.f, sum1 = 0.f;
        #pragma unroll
        for (int nf = 0; nf < 4; ++nf) {
            sfr[nf][0] = __expf(sfr[nf][0] - m0);  sum0 += sfr[nf][0];
            sfr[nf][1] = __expf(sfr[nf][1] - m0);  sum0 += sfr[nf][1];
            sfr[nf][2] = __expf(sfr[nf][2] - m1);  sum1 += sfr[nf][2];
            sfr[nf][3] = __expf(sfr[nf][3] - m1);  sum1 += sfr[nf][3];
        }
        sum0 += __shfl_xor_sync(0xffffffffu, sum0, 1);
        sum0 += __shfl_xor_sync(0xffffffffu, sum0, 2);
        sum1 += __shfl_xor_sync(0xffffffffu, sum1, 1);
        sum1 += __shfl_xor_sync(0xffffffffu, sum1, 2);
        if (t == 0) {
            ssum[half * 64 + rowL]     = sum0;
            ssum[half * 64 + rowL + 8] = sum1;
        }

        // write P (bf16x2 words): word col = half*16 + nf*4 + t
        #pragma unroll
        for (int nf = 0; nf < 4; ++nf) {
            const int pc = half * 16 + nf * 4 + t;
            Pp[rowL * 36 + pc]       = pack_bf16x2(sfr[nf][0], sfr[nf][1]);
            Pp[(rowL + 8) * 36 + pc] = pack_bf16x2(sfr[nf][2], sfr[nf][3]);
        }
        __syncthreads();

        const float f0 = __expf(mrow0 - m0);
        const float f1 = __expf(mrow1 - m1);
        mrow0 = m0;  mrow1 = m1;
        lrow0 = lrow0 * f0 + ssum[rowL]     + ssum[64 + rowL];
        lrow1 = lrow1 * f1 + ssum[rowL + 8] + ssum[64 + rowL + 8];
        #pragma unroll
        for (int nf = 0; nf < 16; ++nf) {
            o[nf][0] *= f0;  o[nf][1] *= f0;
            o[nf][2] *= f1;  o[nf][3] *= f1;
        }

        // ======== O += P * V^T : warp tile 16i x 128c ========
        const int pr = i_sub * 16 + g;
        #pragma unroll
        for (int ks = 0; ks < 4; ++ks) {           // k-steps of 16 j
            const int jw = ks * 8;
            unsigned a0 = Pp[pr * 36 + jw + t];
            unsigned a1 = Pp[(pr + 8) * 36 + jw + t];
            unsigned a2 = Pp[pr * 36 + jw + t + 4];
            unsigned a3 = Pp[(pr + 8) * 36 + jw + t + 4];
            #pragma unroll
            for (int nf = 0; nf < 16; ++nf) {
                const int vc = half * 128 + nf * 8 + g;
                unsigned b0 = Vs[vc * 36 + jw + t];
                unsigned b1 = Vs[vc * 36 + jw + t + 4];
                mma_bf16(o[nf], a0, a1, a2, a3, b0, b1);
            }
        }
    }

    // ======== epilogue: out[b,c,i] = gamma*O/l + x ========
    const float gm = gamma[0];
    const float inv0 = 1.f / lrow0;
    const float inv1 = 1.f / lrow1;
    const float* xb = x + (size_t)b * C_ * N_;
    float* ob = d_out + (size_t)b * C_ * N_;
    const int ig = i0 + rowL;
    #pragma unroll
    for (int nf = 0; nf < 16; ++nf) {
        const int c = half * 128 + nf * 8 + 2 * t;
        size_t off = (size_t)c * N_ + ig;
        ob[off]          = gm * o[nf][0] * inv0 + xb[off];
        ob[off + N_]     = gm * o[nf][1] * inv0 + xb[off + N_];
        ob[off + 8]      = gm * o[nf][2] * inv1 + xb[off + 8];
        ob[off + N_ + 8] = gm * o[nf][3] * inv1 + xb[off + N_ + 8];
    }
}

// ---------------------------------------------------------------------------
extern "C" void kernel_launch(void* const* d_in, const int* in_sizes, int n_in,
                              void* d_out, int out_size)
{
    const float* x     = (const float*)d_in[0];
    const float* Wq    = (const float*)d_in[1];
    const float* bq    = (const float*)d_in[2];
    const float* Wk    = (const float*)d_in[3];
    const float* bk    = (const float*)d_in[4];
    const float* Wv    = (const float*)d_in[5];
    const float* bv    = (const float*)d_in[6];
    const float* gamma = (const float*)d_in[7];
    float* out = (float*)d_out;

    // Unconditional on every call (no static guards — harness rule); this
    // exact pattern passed verification in R3.
    cudaFuncSetAttribute(attn_kernel,
                         cudaFuncAttributeMaxDynamicSharedMemorySize,
                         SMEM_WORDS * (int)sizeof(unsigned));

    dim3 gA(N_ / 64, C_ / 64, 3 * B_);
    proj_kernel<<<gA, 256>>>(x, Wq, bq, Wk, bk, Wv, bv);

    dim3 gB(N_ / 64, B_);
    attn_kernel<<<gB, 256, SMEM_WORDS * (int)sizeof(unsigned)>>>(x, gamma, out);
}